// round 6
// baseline (speedup 1.0000x reference)
#include <cuda_runtime.h>
#include <cuda_bf16.h>
#include <math.h>

// Single fused kernel: Conv3d(3->24,k=3,VALID) + min over depth + bias + channel softmax.
// x: [16,3,32,128,128] -> out: [16,24,1,126,126]
// Block: 256 thr = 4 ch-groups(6ch) x (2 rows x 32 cols, 4px). Grid (63, 16).
// Depth-chunked D=2, ring-6 cp.async pipeline, in-place FFMA2, mkpair reuse across kd.

typedef unsigned long long u64;

#define TH 2
#define ROWS_IN 4
#define SLICE_FLOATS (3 * ROWS_IN * 128)          // 1536
#define RING 6
#define W_FLOATS (81 * 24 * 2)                    // 3888
#define SF_STRIDE 256
#define SMEM_FLOATS (W_FLOATS + RING * SLICE_FLOATS + 16)  // 13120
#define SMEM_BYTES (SMEM_FLOATS * 4)              // 52480

__device__ __forceinline__ void ffma2(u64& d, u64 a, u64 b) {
    asm("fma.rn.f32x2 %0, %1, %2, %0;" : "+l"(d) : "l"(a), "l"(b));
}
__device__ __forceinline__ u64 mkpair(u64 lo_src, u64 hi_src) {
    return (lo_src >> 32) | (hi_src << 32);
}
__device__ __forceinline__ float f2lo(u64 a) { return __uint_as_float((unsigned)(a & 0xffffffffull)); }
__device__ __forceinline__ float f2hi(u64 a) { return __uint_as_float((unsigned)(a >> 32)); }

__device__ __forceinline__ void cpasync16(const float* s_dst, const float* g_src) {
    unsigned saddr = (unsigned)__cvta_generic_to_shared(s_dst);
    asm volatile("cp.async.cg.shared.global [%0], [%1], 16;" :: "r"(saddr), "l"(g_src));
}

__global__ void __launch_bounds__(256, 2)
fused_conv_min_softmax(const float* __restrict__ x,
                       const float* __restrict__ wgt,
                       const float* __restrict__ bias,
                       float* __restrict__ out)
{
    extern __shared__ float smem[];
    float* s_w  = smem;                 // [kd][ci][kh][kw][cc=24][2] duplicated pairs
    float* s_sl = smem + W_FLOATS;      // ring of 6 slices [ci][4][128]

    const int tid = threadIdx.x;
    const int h0  = blockIdx.x * TH;
    const int n   = blockIdx.y;

    const int g     = tid >> 6;         // 0..3 -> channels 6g..6g+5
    const int L     = tid & 63;
    const int r_loc = L >> 5;           // 0..1
    const int j     = L & 31;
    const int w0    = j << 2;           // 4 px per thread

    // ---- weights -> smem duplicated pairs ----
    for (int idx = tid; idx < 1944; idx += 256) {
        int cc = idx / 81, t = idx % 81;
        int ci = t / 27;  t %= 27;
        int kd = t / 9;
        int kh = (t % 9) / 3;
        int kw = t % 3;
        float v = wgt[idx];
        int dst = (((kd * 3 + ci) * 3 + kh) * 3 + kw) * 48 + cc * 2;
        s_w[dst]     = v;
        s_w[dst + 1] = v;
    }

    // ---- async slice loader ----
    auto prefetch_slice = [&](int z, int slot) {
        float* buf = s_sl + slot * SLICE_FLOATS;
        for (int q = tid; q < 384; q += 256) {
            int ci = q >> 7;
            int rr = (q & 127) >> 5;
            int c4 = q & 31;
            cpasync16(buf + (ci * ROWS_IN + rr) * 128 + (c4 << 2),
                      x + ((((size_t)(n * 3 + ci)) * 32 + z) << 14) + ((h0 + rr) << 7) + (c4 << 2));
        }
    };

    prefetch_slice(0, 0);
    prefetch_slice(1, 1);
    prefetch_slice(2, 2);
    prefetch_slice(3, 3);
    asm volatile("cp.async.commit_group;" ::: "memory");
    asm volatile("cp.async.wait_group 0;" ::: "memory");
    __syncthreads();

    const float INF = __int_as_float(0x7f800000);
    float mlo[6][2], mhi[6][2];
    #pragma unroll
    for (int c = 0; c < 6; ++c) {
        mlo[c][0] = INF; mlo[c][1] = INF;
        mhi[c][0] = INF; mhi[c][1] = INF;
    }

    const int    toff = r_loc * 128 + w0;
    const float* wg   = s_w + g * 12;

    int s0 = 0;
    #pragma unroll 1
    for (int c = 0; c < 15; ++c) {
        const int zp = 2 * c + 4;
        if (zp < 32) {
            int sl4 = s0 + 4; if (sl4 >= RING) sl4 -= RING;
            int sl5 = s0 + 5; if (sl5 >= RING) sl5 -= RING;
            prefetch_slice(zp,     sl4);
            prefetch_slice(zp + 1, sl5);
        }
        asm volatile("cp.async.commit_group;" ::: "memory");

        const float* bp[4];
        #pragma unroll
        for (int jj = 0; jj < 4; ++jj) {
            int s = s0 + jj; if (s >= RING) s -= RING;
            bp[jj] = s_sl + s * SLICE_FLOATS + toff;
        }

        u64 acc[2][6][2];
        #pragma unroll
        for (int dz = 0; dz < 2; ++dz)
            #pragma unroll
            for (int cc = 0; cc < 6; ++cc) { acc[dz][cc][0] = 0ull; acc[dz][cc][1] = 0ull; }

        #pragma unroll 1
        for (int ci = 0; ci < 3; ++ci) {
            #pragma unroll
            for (int kh = 0; kh < 3; ++kh) {
                const int ro = (ci * ROWS_IN + kh) * 128;
                u64 A0[4], A1[4], A2[4];
                #pragma unroll
                for (int s = 0; s < 4; ++s) {
                    const float* rp = bp[s] + ro;
                    const ulonglong2 t = *reinterpret_cast<const ulonglong2*>(rp);
                    A0[s] = t.x; A1[s] = t.y;
                    A2[s] = *reinterpret_cast<const u64*>(rp + 4);
                }
                const float* wrow0 = wg + ((ci * 3 + kh) * 144);
                // shifted pairs for slice 0, carried across kd (q(kd) == p(kd+1))
                u64 p0 = mkpair(A0[0], A1[0]);
                u64 p1 = mkpair(A1[0], A2[0]);
                #pragma unroll
                for (int kd = 0; kd < 3; ++kd) {
                    const float* wr = wrow0 + kd * 1296;
                    const u64 q0 = mkpair(A0[kd + 1], A1[kd + 1]);
                    const u64 q1 = mkpair(A1[kd + 1], A2[kd + 1]);
                    #pragma unroll
                    for (int cp = 0; cp < 3; ++cp) {
                        const ulonglong2 W0 = *reinterpret_cast<const ulonglong2*>(wr + 4 * cp);
                        const ulonglong2 W1 = *reinterpret_cast<const ulonglong2*>(wr + 48 + 4 * cp);
                        const ulonglong2 W2 = *reinterpret_cast<const ulonglong2*>(wr + 96 + 4 * cp);
                        const int c0 = 2 * cp, c1 = 2 * cp + 1;
                        // dz=0 (slice kd)
                        ffma2(acc[0][c0][0], A0[kd], W0.x);
                        ffma2(acc[0][c0][1], A1[kd], W0.x);
                        ffma2(acc[0][c1][0], A0[kd], W0.y);
                        ffma2(acc[0][c1][1], A1[kd], W0.y);
                        ffma2(acc[0][c0][0], p0, W1.x);
                        ffma2(acc[0][c0][1], p1, W1.x);
                        ffma2(acc[0][c1][0], p0, W1.y);
                        ffma2(acc[0][c1][1], p1, W1.y);
                        ffma2(acc[0][c0][0], A1[kd], W2.x);
                        ffma2(acc[0][c0][1], A2[kd], W2.x);
                        ffma2(acc[0][c1][0], A1[kd], W2.y);
                        ffma2(acc[0][c1][1], A2[kd], W2.y);
                        // dz=1 (slice kd+1)
                        ffma2(acc[1][c0][0], A0[kd + 1], W0.x);
                        ffma2(acc[1][c0][1], A1[kd + 1], W0.x);
                        ffma2(acc[1][c1][0], A0[kd + 1], W0.y);
                        ffma2(acc[1][c1][1], A1[kd + 1], W0.y);
                        ffma2(acc[1][c0][0], q0, W1.x);
                        ffma2(acc[1][c0][1], q1, W1.x);
                        ffma2(acc[1][c1][0], q0, W1.y);
                        ffma2(acc[1][c1][1], q1, W1.y);
                        ffma2(acc[1][c0][0], A1[kd + 1], W2.x);
                        ffma2(acc[1][c0][1], A2[kd + 1], W2.x);
                        ffma2(acc[1][c1][0], A1[kd + 1], W2.y);
                        ffma2(acc[1][c1][1], A2[kd + 1], W2.y);
                    }
                    p0 = q0;
                    p1 = q1;
                }
            }
        }

        #pragma unroll
        for (int dz = 0; dz < 2; ++dz)
            #pragma unroll
            for (int cc = 0; cc < 6; ++cc)
                #pragma unroll
                for (int p = 0; p < 2; ++p) {
                    mlo[cc][p] = fminf(mlo[cc][p], f2lo(acc[dz][cc][p]));
                    mhi[cc][p] = fminf(mhi[cc][p], f2hi(acc[dz][cc][p]));
                }

        asm volatile("cp.async.wait_group 0;" ::: "memory");
        __syncthreads();

        s0 += 2; if (s0 >= RING) s0 -= RING;
    }

    // ---- min + bias -> smem transpose buffer sf[24][SF_STRIDE] ----
    __syncthreads();
    float* sf = smem;
    {
        const int p0 = r_loc * 126 + w0;
        #pragma unroll
        for (int cc = 0; cc < 6; ++cc) {
            const int co = g * 6 + cc;
            const float bv = __ldg(&bias[co]);
            float* row = sf + co * SF_STRIDE + p0;
            *reinterpret_cast<float2*>(row) = make_float2(mlo[cc][0] + bv, mhi[cc][0] + bv);
            if (w0 + 2 < 126)
                *reinterpret_cast<float2*>(row + 2) = make_float2(mlo[cc][1] + bv, mhi[cc][1] + bv);
        }
    }
    __syncthreads();

    // ---- softmax over 24 channels ----
    if (tid < 252) {
        const int px = tid;
        float v[24];
        float m = -INF;
        #pragma unroll
        for (int cc = 0; cc < 24; ++cc) { v[cc] = sf[cc * SF_STRIDE + px]; m = fmaxf(m, v[cc]); }
        float s = 0.f;
        #pragma unroll
        for (int cc = 0; cc < 24; ++cc) { v[cc] = __expf(v[cc] - m); s += v[cc]; }
        const float inv = 1.0f / s;
        float* op = out + (size_t)n * 24 * 15876 + (size_t)h0 * 126 + px;
        #pragma unroll
        for (int cc = 0; cc < 24; ++cc)
            op[(size_t)cc * 15876] = v[cc] * inv;
    }
}

extern "C" void kernel_launch(void* const* d_in, const int* in_sizes, int n_in,
                              void* d_out, int out_size) {
    const float* x    = (const float*)d_in[0];
    const float* wgt  = (const float*)d_in[1];
    const float* bias = (const float*)d_in[2];
    float* out        = (float*)d_out;

    cudaFuncSetAttribute(fused_conv_min_softmax,
                         cudaFuncAttributeMaxDynamicSharedMemorySize, SMEM_BYTES);

    dim3 grid(63, 16);
    fused_conv_min_softmax<<<grid, 256, SMEM_BYTES>>>(x, wgt, bias, out);
}

// round 7
// speedup vs baseline: 1.2520x; 1.2520x over previous
#include <cuda_runtime.h>
#include <cuda_bf16.h>
#include <math.h>

// Fused Conv3d(3->24,k=3,VALID) + min over depth + bias + channel softmax.
// x: [16,3,32,128,128] -> out: [16,24,1,126,126]
//
// f32x2 lanes = (depth d, depth d+1). Slices stored depth-interleaved in smem:
// I_z[px] = (x_z[px], x_{z+1}[px]) so every x operand (incl. kw shifts) is one
// aligned LDS.64. No register pair assembly anywhere in the inner loop.
// Chunk c computes output depths (2c, 2c+1) using I_{2c+kd}, kd=0..2.

typedef unsigned long long u64;
typedef unsigned int u32;

#define TH 2
#define ROWS 4
#define GRP 34                         // floats per 16-px group (32 data + 2 pad)
#define ROWF (8 * GRP)                 // 272 floats per interleaved row
#define IBUF_FLOATS (3 * ROWS * ROWF)  // 3264
#define RING 6
#define W_FLOATS (81 * 24 * 2)         // 3888 duplicated weight pairs
#define SF_STRIDE 256
#define SMEM_FLOATS (W_FLOATS + RING * IBUF_FLOATS + 16)  // 23488
#define SMEM_BYTES (SMEM_FLOATS * 4)   // 93952

__device__ __forceinline__ void ffma2(u64& d, u64 a, u64 b) {
    asm("fma.rn.f32x2 %0, %1, %2, %0;" : "+l"(d) : "l"(a), "l"(b));
}
__device__ __forceinline__ float f2lo(u64 a) { return __uint_as_float((unsigned)(a & 0xffffffffull)); }
__device__ __forceinline__ float f2hi(u64 a) { return __uint_as_float((unsigned)(a >> 32)); }

__device__ __forceinline__ void cpasync4(const float* s_dst, const float* g_src) {
    u32 sa = (u32)__cvta_generic_to_shared(s_dst);
    asm volatile("cp.async.ca.shared.global [%0], [%1], 4;" :: "r"(sa), "l"(g_src));
}

__global__ void __launch_bounds__(256, 2)
fused_conv_min_softmax(const float* __restrict__ x,
                       const float* __restrict__ wgt,
                       const float* __restrict__ bias,
                       float* __restrict__ out)
{
    extern __shared__ float smem[];
    float* s_w = smem;                  // [kd][ci][kh][kw][24ch][2] dup pairs
    float* s_I = smem + W_FLOATS;       // ring of 6 interleaved slice-pair bufs

    const int tid = threadIdx.x;
    const int h0  = blockIdx.x * TH;
    const int n   = blockIdx.y;

    const int g     = tid >> 6;         // channel group: co = 6g..6g+5
    const int L     = tid & 63;
    const int r_loc = L >> 5;           // output row 0..1
    const int j     = L & 31;
    const int w0    = j << 2;           // 4 px per thread

    // ---- weights -> smem duplicated pairs ----
    for (int idx = tid; idx < 1944; idx += 256) {
        int cc = idx / 81;
        int t  = idx % 81;
        int ci = t / 27;  t %= 27;
        int kd = t / 9;
        int kh = (t % 9) / 3;
        int kw = t % 3;
        float v = wgt[idx];
        int dst = (((kd * 3 + ci) * 3 + kh) * 3 + kw) * 48 + cc * 2;
        s_w[dst]     = v;
        s_w[dst + 1] = v;
    }

    // per-thread padded x offsets for px = w0..w0+5 (float units)
    int offc[6];
    #pragma unroll
    for (int c = 0; c < 6; ++c) {
        int px = w0 + c;
        offc[c] = 2 * (px + (px >> 4));
    }

    // ---- interleaving loader: slice z -> lo of I_z, hi of I_{z-1} ----
    auto prefetch = [&](int z) {
        float* lo = s_I + (z % 6) * IBUF_FLOATS;
        float* hi = s_I + ((z + 5) % 6) * IBUF_FLOATS;
        const bool lo_en = (z <= 30);
        const bool hi_en = (z >= 1);
        #pragma unroll
        for (int i = 0; i < 6; ++i) {              // 1536 floats / 256 thr
            int q   = tid + i * 256;
            int ci  = q >> 9;
            int row = (q >> 7) & 3;
            int px  = q & 127;
            const float* gp = x + ((((size_t)(n * 3 + ci)) * 32 + z) << 14)
                                + ((h0 + row) << 7) + px;
            int fo = (ci * ROWS + row) * ROWF + 2 * (px + (px >> 4));
            if (lo_en) cpasync4(lo + fo,     gp);
            if (hi_en) cpasync4(hi + fo + 1, gp);
        }
    };

    prefetch(0); prefetch(1); prefetch(2); prefetch(3);
    asm volatile("cp.async.commit_group;" ::: "memory");
    asm volatile("cp.async.wait_group 0;" ::: "memory");
    __syncthreads();

    const float INF = __int_as_float(0x7f800000);
    float mn[4][6];
    #pragma unroll
    for (int p = 0; p < 4; ++p)
        #pragma unroll
        for (int cc = 0; cc < 6; ++cc) mn[p][cc] = INF;

    const float* wg = s_w + g * 12;     // channel-group weight base

    int s0 = 0;                          // ring slot of I_{2c}
    #pragma unroll 1
    for (int c = 0; c < 15; ++c) {
        const int z4 = 2 * c + 4;
        if (z4 < 32) { prefetch(z4); prefetch(z4 + 1); }
        asm volatile("cp.async.commit_group;" ::: "memory");

        const float* ib[3];
        #pragma unroll
        for (int k = 0; k < 3; ++k) {
            int s = s0 + k; if (s >= RING) s -= RING;
            ib[k] = s_I + s * IBUF_FLOATS;
        }

        u64 acc[4][6];
        #pragma unroll
        for (int p = 0; p < 4; ++p)
            #pragma unroll
            for (int cc = 0; cc < 6; ++cc) acc[p][cc] = 0ull;

        #pragma unroll 1
        for (int ci = 0; ci < 3; ++ci) {
            #pragma unroll
            for (int kh = 0; kh < 3; ++kh) {
                const int    rw = (ci * ROWS + r_loc + kh) * ROWF;
                const float* wp = wg + (ci * 3 + kh) * 144;
                #pragma unroll
                for (int kd = 0; kd < 3; ++kd) {
                    const float* bb = ib[kd] + rw;
                    u64 P[6];
                    #pragma unroll
                    for (int cix = 0; cix < 6; ++cix)
                        P[cix] = *reinterpret_cast<const u64*>(bb + offc[cix]);
                    #pragma unroll
                    for (int kw = 0; kw < 3; ++kw) {
                        const float* wt = wp + kd * 1296 + kw * 48;
                        #pragma unroll
                        for (int cp = 0; cp < 3; ++cp) {
                            const ulonglong2 W =
                                *reinterpret_cast<const ulonglong2*>(wt + cp * 4);
                            #pragma unroll
                            for (int p = 0; p < 4; ++p) {
                                ffma2(acc[p][2 * cp],     P[kw + p], W.x);
                                ffma2(acc[p][2 * cp + 1], P[kw + p], W.y);
                            }
                        }
                    }
                }
            }
        }

        #pragma unroll
        for (int p = 0; p < 4; ++p)
            #pragma unroll
            for (int cc = 0; cc < 6; ++cc) {
                float v = fminf(f2lo(acc[p][cc]), f2hi(acc[p][cc]));
                mn[p][cc] = fminf(mn[p][cc], v);
            }

        asm volatile("cp.async.wait_group 0;" ::: "memory");
        __syncthreads();

        s0 += 2; if (s0 >= RING) s0 -= RING;
    }

    // ---- min + bias -> smem transpose buffer sf[24][SF_STRIDE] ----
    float* sf = smem;                    // all smem reads complete (loop-end sync)
    #pragma unroll
    for (int cc = 0; cc < 6; ++cc) {
        const int co = g * 6 + cc;
        const float bv = __ldg(&bias[co]);
        float* row = sf + co * SF_STRIDE + r_loc * 126;
        #pragma unroll
        for (int p = 0; p < 4; ++p) {
            int col = w0 + p;
            if (col < 126) row[col] = mn[p][cc] + bv;
        }
    }
    __syncthreads();

    // ---- softmax over 24 channels ----
    if (tid < 252) {
        const int px = tid;              // r*126 + w, r in 0..1
        float v[24];
        float m = -INF;
        #pragma unroll
        for (int cc = 0; cc < 24; ++cc) { v[cc] = sf[cc * SF_STRIDE + px]; m = fmaxf(m, v[cc]); }
        float s = 0.f;
        #pragma unroll
        for (int cc = 0; cc < 24; ++cc) { v[cc] = __expf(v[cc] - m); s += v[cc]; }
        const float inv = 1.0f / s;
        float* op = out + (size_t)n * 24 * 15876 + (size_t)h0 * 126 + px;
        #pragma unroll
        for (int cc = 0; cc < 24; ++cc)
            op[(size_t)cc * 15876] = v[cc] * inv;
    }
}

extern "C" void kernel_launch(void* const* d_in, const int* in_sizes, int n_in,
                              void* d_out, int out_size) {
    const float* x    = (const float*)d_in[0];
    const float* wgt  = (const float*)d_in[1];
    const float* bias = (const float*)d_in[2];
    float* out        = (float*)d_out;

    cudaFuncSetAttribute(fused_conv_min_softmax,
                         cudaFuncAttributeMaxDynamicSharedMemorySize, SMEM_BYTES);

    dim3 grid(63, 16);
    fused_conv_min_softmax<<<grid, 256, SMEM_BYTES>>>(x, wgt, bias, out);
}

// round 9
// speedup vs baseline: 1.7835x; 1.4246x over previous
#include <cuda_runtime.h>
#include <cuda_bf16.h>
#include <math.h>

// Tensor-core (mma.sync bf16, hi/lo split) implementation.
// CTA = one (n,h) output row. Per depth d: D[co32, px128] = sum_kd W.X(z=d+kd).
// Weights persistent as ldmatrix A-fragments; X slices built bf16(hi,lo) in smem,
// ring of 4, reused by 3 depths. Min over depth in regs; softmax epilogue.

typedef unsigned int u32;

#define XROW 272                       // bytes per k-row (128 px bf16 + pad)
#define XPART (32 * XROW)              // 8704: one part (hi or lo) of a slice
#define XSLOT (2 * XPART)              // 17408
#define OFF_X 0
#define OFF_W (4 * XSLOT)              // 69632
#define WROW 192                       // 96 k bf16
#define WPART (32 * WROW)              // 6144
#define SMEM_TOTAL (OFF_W + 2 * WPART + 64)   // 81984

__device__ __forceinline__ void ldsm4(u32* r, u32 a) {
    asm volatile("ldmatrix.sync.aligned.m8n8.x4.shared.b16 {%0,%1,%2,%3}, [%4];"
        : "=r"(r[0]), "=r"(r[1]), "=r"(r[2]), "=r"(r[3]) : "r"(a));
}
__device__ __forceinline__ void ldsm4t(u32* r, u32 a) {
    asm volatile("ldmatrix.sync.aligned.m8n8.x4.trans.shared.b16 {%0,%1,%2,%3}, [%4];"
        : "=r"(r[0]), "=r"(r[1]), "=r"(r[2]), "=r"(r[3]) : "r"(a));
}
__device__ __forceinline__ void mma_bf16(float* d, const u32* a, u32 b0, u32 b1) {
    asm volatile(
        "mma.sync.aligned.m16n8k16.row.col.f32.bf16.bf16.f32 "
        "{%0,%1,%2,%3}, {%4,%5,%6,%7}, {%8,%9}, {%0,%1,%2,%3};"
        : "+f"(d[0]), "+f"(d[1]), "+f"(d[2]), "+f"(d[3])
        : "r"(a[0]), "r"(a[1]), "r"(a[2]), "r"(a[3]), "r"(b0), "r"(b1));
}

extern "C" __global__ void __launch_bounds__(256, 2)
conv_mma(const float* __restrict__ x, const float* __restrict__ wgt,
         const float* __restrict__ bias, float* __restrict__ out)
{
    extern __shared__ char sm[];
    const u32 sb = (u32)__cvta_generic_to_shared(sm);
    const int tid   = threadIdx.x;
    const int lane  = tid & 31;
    const int wid   = tid >> 5;
    const int mtile = wid & 1;         // co rows mtile*16..+15
    const int npair = wid >> 1;        // px base npair*32 (4 n8-tiles)
    const int h = blockIdx.x;
    const int n = blockIdx.y;

    // zero all smem (k-pad rows 27-31, co-pad 24-31, px pad stay 0 forever)
    for (int i = tid; i < SMEM_TOTAL / 16; i += 256)
        *reinterpret_cast<float4*>(sm + i * 16) = make_float4(0.f, 0.f, 0.f, 0.f);
    __syncthreads();

    // ---- weights -> smem bf16 hi/lo: W[part][co][k], k = kd*32 + (ci*3+kh)*3+kw ----
    for (int e = tid; e < 1944; e += 256) {
        int co = e / 81, tap = e % 81;
        int ci = tap / 27, r = tap % 27;
        int kd = r / 9, kh = (r % 9) / 3, kw = r % 3;
        float v = wgt[e];
        __nv_bfloat16 hb = __float2bfloat16(v);
        float lo = v - __bfloat162float(hb);
        __nv_bfloat16 lb = __float2bfloat16(lo);
        int k = kd * 32 + (ci * 3 + kh) * 3 + kw;
        *reinterpret_cast<__nv_bfloat16*>(sm + OFF_W +         co * WROW + k * 2) = hb;
        *reinterpret_cast<__nv_bfloat16*>(sm + OFF_W + WPART + co * WROW + k * 2) = lb;
    }

    // ---- slice builder: z -> slot. rows k=r9*3+kw (r9=ci*3+kh), shifted copies ----
    auto build = [&](int z, int slot) {
        char* base = sm + OFF_X + slot * XSLOT;
        #pragma unroll
        for (int it = 0; it < 5; ++it) {
            int idx = tid + it * 256;
            if (idx < 1152) {
                int r9 = idx >> 7, px = idx & 127;
                int ci = r9 / 3, kh = r9 % 3;
                float v = __ldg(x + ((size_t)((n * 3 + ci) * 32 + z) << 14)
                                  + ((h + kh) << 7) + px);
                __nv_bfloat16 hb = __float2bfloat16(v);
                __nv_bfloat16 lb = __float2bfloat16(v - __bfloat162float(hb));
                #pragma unroll
                for (int kw = 0; kw < 3; ++kw) {
                    int col = px - kw;
                    if (col >= 0) {
                        int k = r9 * 3 + kw;
                        *reinterpret_cast<__nv_bfloat16*>(base + k * XROW + col * 2) = hb;
                        *reinterpret_cast<__nv_bfloat16*>(base + XPART + k * XROW + col * 2) = lb;
                    }
                }
            }
        }
    };

    build(0, 0); build(1, 1); build(2, 2);
    __syncthreads();

    // ---- persistent A fragments (weights): ah/al[kd][ks][4] ----
    u32 ah[3][2][4], al[3][2][4];
    {
        u32 rowb = sb + OFF_W + (u32)((mtile * 16 + (lane & 15)) * WROW + (lane >> 4) * 16);
        #pragma unroll
        for (int kd = 0; kd < 3; ++kd)
            #pragma unroll
            for (int ks = 0; ks < 2; ++ks) {
                ldsm4(ah[kd][ks], rowb + (u32)((kd * 32 + ks * 16) * 2));
                ldsm4(al[kd][ks], rowb + (u32)(WPART + (kd * 32 + ks * 16) * 2));
            }
    }

    // B-side per-lane base: lanes 0-7:k0-7@n0, 8-15:k8-15@n0, 16-23:k0-7@n8, 24-31:k8-15@n8
    const int krow = ((lane >> 3) & 1) * 8 + (lane & 7);
    const int pxo  = (lane >> 4) * 8;
    const u32 boff = sb + OFF_X + (u32)(krow * XROW + (npair * 32 + pxo) * 2);

    const float INF = __int_as_float(0x7f800000);
    float mn[4][4];
    #pragma unroll
    for (int t = 0; t < 4; ++t)
        #pragma unroll
        for (int e = 0; e < 4; ++e) mn[t][e] = INF;

    for (int d = 0; d < 30; ++d) {
        float D[4][4];
        #pragma unroll
        for (int t = 0; t < 4; ++t)
            #pragma unroll
            for (int e = 0; e < 4; ++e) D[t][e] = 0.f;

        #pragma unroll
        for (int kd = 0; kd < 3; ++kd) {
            const u32 sbase = boff + (u32)(((d + kd) & 3) * XSLOT);
            #pragma unroll
            for (int ks = 0; ks < 2; ++ks) {
                const u32 a0 = sbase + (u32)(ks * 16 * XROW);
                u32 bh[8], bl[8];
                ldsm4t(bh,     a0);            // ntiles 0,1 (px0..15)
                ldsm4t(bh + 4, a0 + 32);       // ntiles 2,3 (px16..31)
                ldsm4t(bl,     a0 + XPART);
                ldsm4t(bl + 4, a0 + XPART + 32);
                #pragma unroll
                for (int nt = 0; nt < 4; ++nt) {
                    mma_bf16(D[nt], ah[kd][ks], bh[nt * 2], bh[nt * 2 + 1]);  // hh
                    mma_bf16(D[nt], al[kd][ks], bh[nt * 2], bh[nt * 2 + 1]);  // lh
                    mma_bf16(D[nt], ah[kd][ks], bl[nt * 2], bl[nt * 2 + 1]);  // hl
                }
            }
        }

        #pragma unroll
        for (int t = 0; t < 4; ++t)
            #pragma unroll
            for (int e = 0; e < 4; ++e) mn[t][e] = fminf(mn[t][e], D[t][e]);

        if (d + 3 < 32) build(d + 3, (d + 3) & 3);
        __syncthreads();   // build(d+3) visible before depth d+1 reads slot (d+3)&3
    }

    // ---- scatter min to sf[px128][co32], then bias+softmax ----
    float* sf = reinterpret_cast<float*>(sm);   // aliases X region (reads done)
    {
        const int pxb = npair * 32 + (lane & 3) * 2;
        const int cob = mtile * 16 + (lane >> 2);
        #pragma unroll
        for (int nt = 0; nt < 4; ++nt) {
            int px = pxb + nt * 8;
            sf[px * 32 + cob]           = mn[nt][0];
            sf[(px + 1) * 32 + cob]     = mn[nt][1];
            sf[px * 32 + cob + 8]       = mn[nt][2];
            sf[(px + 1) * 32 + cob + 8] = mn[nt][3];
        }
    }
    __syncthreads();

    if (tid < 126) {
        float v[24];
        float m = -INF;
        #pragma unroll
        for (int c = 0; c < 24; ++c) {
            v[c] = sf[tid * 32 + c] + __ldg(&bias[c]);
            m = fmaxf(m, v[c]);
        }
        float s = 0.f;
        #pragma unroll
        for (int c = 0; c < 24; ++c) { v[c] = __expf(v[c] - m); s += v[c]; }
        const float inv = 1.0f / s;
        float* op = out + (size_t)n * 24 * 15876 + (size_t)h * 126 + tid;
        #pragma unroll
        for (int c = 0; c < 24; ++c)
            op[(size_t)c * 15876] = v[c] * inv;
    }
}

extern "C" void kernel_launch(void* const* d_in, const int* in_sizes, int n_in,
                              void* d_out, int out_size) {
    const float* x    = (const float*)d_in[0];
    const float* wgt  = (const float*)d_in[1];
    const float* bias = (const float*)d_in[2];
    float* out        = (float*)d_out;

    cudaFuncSetAttribute(conv_mma,
                         cudaFuncAttributeMaxDynamicSharedMemorySize, SMEM_TOTAL);

    dim3 grid(126, 16);   // (h, n)
    conv_mma<<<grid, 256, SMEM_TOTAL>>>(x, wgt, bias, out);
}